// round 16
// baseline (speedup 1.0000x reference)
#include <cuda_runtime.h>
#include <cuda_bf16.h>
#include <cstdint>

#define NF 27
#define ND 128
#define NB 16384
#define OUT_ROW 479            // 128 + 27*26/2
#define WPC 4                  // warps per CTA; 1 sample per warp
// per-warp smem: hi tile 27x256B (6912B, swizzled) then lo tile (6912B)
#define TILE_B 6912
#define WARPSM (2 * TILE_B)    // 13824
#define CTASM  (WPC * WARPSM)  // 55296 -> 4 CTAs/SM

// pack two f32 -> bf16x2 (elem order: lo first in memory)
__device__ __forceinline__ uint32_t pack_bf16x2(float lo, float hi) {
    uint32_t r;
    asm("cvt.rn.bf16x2.f32 %0, %1, %2;" : "=r"(r) : "f"(hi), "f"(lo));
    return r;
}
__device__ __forceinline__ void ldm_x4(uint32_t* r, uint32_t addr) {
    asm volatile("ldmatrix.sync.aligned.m8n8.x4.shared.b16 {%0,%1,%2,%3}, [%4];"
                 : "=r"(r[0]), "=r"(r[1]), "=r"(r[2]), "=r"(r[3]) : "r"(addr));
}
__device__ __forceinline__ void mma_bf16(float* d, const uint32_t* a,
                                         uint32_t b0, uint32_t b1) {
    asm volatile("mma.sync.aligned.m16n8k16.row.col.f32.bf16.bf16.f32 "
                 "{%0,%1,%2,%3}, {%4,%5,%6,%7}, {%8,%9}, {%0,%1,%2,%3};"
                 : "+f"(d[0]), "+f"(d[1]), "+f"(d[2]), "+f"(d[3])
                 : "r"(a[0]), "r"(a[1]), "r"(a[2]), "r"(a[3]), "r"(b0), "r"(b1));
}

extern "C" __global__ void __launch_bounds__(WPC * 32, 4)
interaction_kernel(const float* __restrict__ dense,
                   const float* __restrict__ sparse,
                   float* __restrict__ out)
{
    extern __shared__ char smem[];
    uint32_t sb;
    asm("{ .reg .u64 t; cvta.to.shared.u64 t, %1; cvt.u32.u64 %0, t; }"
        : "=r"(sb) : "l"(smem));
    const int warp = threadIdx.x >> 5;
    const int lane = threadIdx.x & 31;
    const uint32_t sHi = sb + warp * WARPSM;       // 27 rows x 256B, swizzled
    const uint32_t sLo = sHi + TILE_B;

    const int b = blockIdx.x * WPC + warp;         // sample
    float* orow = out + (size_t)b * OUT_ROW;

    // ---- fill: convert fp32 row -> bf16 hi/lo, swizzled STS.
    // element (row f, 16B-chunk c): byte = f*256 + ((c ^ (f&7))<<4)
    // lane covers dims 4*lane..+3 -> chunk c=lane>>1, half lane&1
    {
        const uint32_t hsel = (uint32_t)(lane & 1) << 3;
        #pragma unroll
        for (int bt = 0; bt < 3; ++bt) {
            float4 v[9];
            #pragma unroll
            for (int r = 0; r < 9; ++r) {
                const int f = bt * 9 + r;
                const float* src = (f == 0)
                    ? dense  + (size_t)b * ND
                    : sparse + ((size_t)b * 26 + (f - 1)) * ND;
                v[r] = *reinterpret_cast<const float4*>(src + lane * 4);
            }
            #pragma unroll
            for (int r = 0; r < 9; ++r) {
                const int f = bt * 9 + r;
                if (f == 0) {                       // dense passthrough (4B-aligned row)
                    orow[lane*4+0] = v[r].x; orow[lane*4+1] = v[r].y;
                    orow[lane*4+2] = v[r].z; orow[lane*4+3] = v[r].w;
                }
                uint32_t h0 = pack_bf16x2(v[r].x, v[r].y);
                uint32_t h1 = pack_bf16x2(v[r].z, v[r].w);
                float hx = __uint_as_float(h0 << 16);
                float hy = __uint_as_float(h0 & 0xffff0000u);
                float hz = __uint_as_float(h1 << 16);
                float hw = __uint_as_float(h1 & 0xffff0000u);
                uint32_t l0 = pack_bf16x2(v[r].x - hx, v[r].y - hy);
                uint32_t l1 = pack_bf16x2(v[r].z - hz, v[r].w - hw);
                const uint32_t off = (uint32_t)f * 256u
                    + ((uint32_t)(((lane >> 1) ^ (f & 7))) << 4) + hsel;
                asm volatile("st.shared.v2.b32 [%0], {%1,%2};"
                             :: "r"(sHi + off), "r"(h0), "r"(h1) : "memory");
                asm volatile("st.shared.v2.b32 [%0], {%1,%2};"
                             :: "r"(sLo + off), "r"(l0), "r"(l1) : "memory");
            }
        }
    }
    __syncwarp();

    // ---- ldmatrix addressing (A-fragments only; B-frags are register aliases)
    const int g4 = lane >> 3;                      // ldmatrix lane-group 0..3
    const int lr = lane & 7;
    // A x4 (M-tile mt): m0 rows0-7 c0 | m1 rows8-15 c0 | m2 rows0-7 c1 | m3 rows8-15 c1
    const uint32_t rowA = (uint32_t)(8 * (g4 & 1) + lr);
    const uint32_t cselA = (uint32_t)(g4 >> 1);
    uint32_t aBase[2];
    #pragma unroll
    for (int mt = 0; mt < 2; ++mt) {
        uint32_t rA = rowA + 16u * mt;
        if (rA > 26u) rA = 26u;                    // clamp: rows 27-31 are garbage reads
        aBase[mt] = sHi + rA * 256u;
    }

    // 6 needed D tiles: t=0..3 -> (mt0,nt t); t=4,5 -> (mt1, nt t-2)
    float d[6][4];
    #pragma unroll
    for (int t = 0; t < 6; ++t)
        #pragma unroll
        for (int ri = 0; ri < 4; ++ri) d[t][ri] = 0.0f;

    // ---- mainloop: 8 k-tiles; D = Ah*Bh^T + Ah*Bl^T + Al*Bh^T
    // B-frag aliasing (Gram symmetry): for n-tile nt, b0 = A[nt>>1][nt&1],
    // b1 = A[nt>>1][2+(nt&1)]  (same lane layout as A-frag regs)
    #pragma unroll
    for (int kt = 0; kt < 8; ++kt) {
        uint32_t Ah[2][4], Al[2][4];
        const uint32_t ca = (((uint32_t)(2 * kt) + cselA) ^ (uint32_t)lr) << 4;
        #pragma unroll
        for (int mt = 0; mt < 2; ++mt) {
            ldm_x4(Ah[mt], aBase[mt] + ca);
            ldm_x4(Al[mt], aBase[mt] + TILE_B + ca);
        }
        #pragma unroll
        for (int t = 0; t < 6; ++t) {
            const int mt = (t < 4) ? 0 : 1;
            const int nt = (t < 4) ? t : (t - 2);
            const int bq = nt >> 1, bh = nt & 1;
            const uint32_t bh0 = Ah[bq][bh], bh1 = Ah[bq][2 + bh];
            const uint32_t bl0 = Al[bq][bh], bl1 = Al[bq][2 + bh];
            mma_bf16(d[t], Ah[mt], bh0, bh1);
            mma_bf16(d[t], Ah[mt], bl0, bl1);
            mma_bf16(d[t], Al[mt], bh0, bh1);
        }
    }

    // ---- epilogue: D fragment (i,j) -> strict upper triangle scatter
    // lane l: i = 16mt + l/4 + 8*(ri>>1), j = 8nt + 2*(l%4) + (ri&1)
    const int g = lane >> 2, tig = lane & 3;
    #pragma unroll
    for (int t = 0; t < 6; ++t) {
        const int mt = (t < 4) ? 0 : 1;
        const int nt = (t < 4) ? t : (t - 2);
        #pragma unroll
        for (int ri = 0; ri < 4; ++ri) {
            const int i = 16 * mt + g + 8 * (ri >> 1);
            const int j = 8 * nt + 2 * tig + (ri & 1);
            if (i < NF && j < NF && j > i) {
                const int p = 26 * i - ((i * (i - 1)) >> 1) + (j - i - 1);
                orow[ND + p] = d[t][ri];
            }
        }
    }
}

extern "C" void kernel_launch(void* const* d_in, const int* in_sizes, int n_in,
                              void* d_out, int out_size)
{
    const float* dense  = (const float*)d_in[0];
    const float* sparse = (const float*)d_in[1];
    float* out = (float*)d_out;

    cudaFuncSetAttribute(interaction_kernel,
                         cudaFuncAttributeMaxDynamicSharedMemorySize, CTASM);
    interaction_kernel<<<NB / WPC, WPC * 32, CTASM>>>(dense, sparse, out);
}